// round 5
// baseline (speedup 1.0000x reference)
#include <cuda_runtime.h>
#include <cuda_bf16.h>
#include <math.h>
#include <stdint.h>

#define NQ 16384
#define NC 8192
#define DD 256
#define ZELEMS 4194304
#define LOSS_OFF 4194304
#define PERP_OFF 4194305
#define UNIQ_OFF 4194306
#define IDX_OFF  4194307

#define QS   18.0f
#define C2S  0.006172839506172839f   // 2/(QS*QS)
#define MARGIN 6.0f

// ---------------- device scratch ----------------
__device__ float    g_cnorm[NC];
__device__ int      g_counts[NC];
__device__ int      g_idx[NQ];
__device__ float    g_lpart[16384];
__device__ uint32_t g_w8T[64 * NC];   // packed int8 codebook, [kchunk][code]
__device__ float    g_zT[NQ * DD];    // channel-last queries (rescore)
__device__ float    g_bm8[1024 * NQ]; // per-8-code bin minima, bin-major

// ---------------- helpers ----------------
__device__ __forceinline__ uint32_t s2u(const void* p) {
    uint32_t a;
    asm("{ .reg .u64 t; cvta.to.shared.u64 t, %1; cvt.u32.u64 %0, t; }" : "=r"(a) : "l"(p));
    return a;
}
#define CPASYNC(dst, src) \
    asm volatile("cp.async.cg.shared.global [%0], [%1], 16;" :: "r"(dst), "l"(src))
#define CPCOMMIT() asm volatile("cp.async.commit_group;")
#define CPWAIT(n)  asm volatile("cp.async.wait_group %0;" :: "n"(n))

__device__ __forceinline__ int8_t q8(float v) {
    int q = __float2int_rn(v * QS);
    return (int8_t)max(-127, min(127, q));
}

// smem: A 32K | B0 32K | B1 32K | cn 32K
#define SM_A  0
#define SM_B0 32768
#define SM_B1 65536
#define SM_CN 98304
#define SMEM_SZ 131072

// ---------------- prep ----------------
__global__ void k_zero() {
    int t = blockIdx.x * blockDim.x + threadIdx.x;
    if (t < NC) g_counts[t] = 0;
}

__global__ void k_cnorm(const float* __restrict__ w) {
    int warp = threadIdx.x >> 5, lane = threadIdx.x & 31;
    int c = blockIdx.x * 8 + warp;
    const float* row = w + c * DD;
    float s = 0.f;
#pragma unroll
    for (int j = 0; j < 8; j++) { float v = row[lane + j * 32]; s += v * v; }
#pragma unroll
    for (int off = 16; off; off >>= 1) s += __shfl_xor_sync(0xffffffffu, s, off);
    if (lane == 0) g_cnorm[c] = s;
}

// quantize + pack + transpose codebook -> [chunk][code]
__global__ void k_w8t(const float* __restrict__ w) {
    int x = blockIdx.x * 256 + threadIdx.x;      // 0..524287
    int code = x & 8191, chunk = x >> 13;
    float4 v = *(const float4*)(w + (size_t)code * DD + chunk * 4);
    uint32_t p = (uint32_t)(uint8_t)q8(v.x) | ((uint32_t)(uint8_t)q8(v.y) << 8) |
                 ((uint32_t)(uint8_t)q8(v.z) << 16) | ((uint32_t)(uint8_t)q8(v.w) << 24);
    g_w8T[chunk * NC + code] = p;
}

__global__ void k_zt(const float* __restrict__ z) {
    __shared__ float tile[32][33];
    int s0 = blockIdx.x * 32, c0 = blockIdx.y * 32, b = blockIdx.z;
    int tx = threadIdx.x, ty = threadIdx.y;
#pragma unroll
    for (int r = 0; r < 4; r++)
        tile[ty + r * 8][tx] = z[b * 1048576 + (c0 + ty + r * 8) * 4096 + s0 + tx];
    __syncthreads();
#pragma unroll
    for (int r = 0; r < 4; r++)
        g_zT[(b * 4096 + s0 + ty + r * 8) * DD + c0 + tx] = tile[tx][ty + r * 8];
}

// ---------------- dp4a distance filter ----------------
// grid 128 (one 128-query slab each), 256 thr = 16 tx (bins) x 16 ty (q-octets).
__global__ void __launch_bounds__(256, 1) k_tc(const float* __restrict__ z) {
    extern __shared__ char smem[];
    uint32_t sb = s2u(smem);
    float* cn_s = (float*)(smem + SM_CN);

    int tid = threadIdx.x;
    int tx = tid & 15, ty = tid >> 4;
    int qbase = blockIdx.x * 128;
    int b = blockIdx.x >> 5, s0 = (blockIdx.x & 31) * 128;
    const float* zb = z + b * 1048576 + s0;

    // prefetch B tile 0 (codes 0..127, all 64 chunks) : [chunk][128 codes]
    {
#pragma unroll
        for (int i = 0; i < 8; i++) {
            int e = tid + i * 256;
            int row = e >> 5, c16 = e & 31;
            CPASYNC(sb + SM_B0 + row * 512 + c16 * 16,
                    (const char*)g_w8T + (size_t)row * 32768 + c16 * 16);
        }
        CPCOMMIT();
    }
    // cnorm -> smem
    {
        const float4* src = (const float4*)g_cnorm;
        float4* dst = (float4*)cn_s;
        for (int i = tid; i < 2048; i += 256) dst[i] = src[i];
    }
    // A fill: pack queries int8, layout [q][chunk^( (q&7)<<2 )] uint32
    for (int e = tid; e < 8192; e += 256) {
        int q = e & 127, chunk = e >> 7;
        float v0 = zb[(chunk * 4 + 0) * 4096 + q];
        float v1 = zb[(chunk * 4 + 1) * 4096 + q];
        float v2 = zb[(chunk * 4 + 2) * 4096 + q];
        float v3 = zb[(chunk * 4 + 3) * 4096 + q];
        uint32_t p = (uint32_t)(uint8_t)q8(v0) | ((uint32_t)(uint8_t)q8(v1) << 8) |
                     ((uint32_t)(uint8_t)q8(v2) << 16) | ((uint32_t)(uint8_t)q8(v3) << 24);
        int sc = chunk ^ ((q & 7) << 2);
        *(uint32_t*)(smem + SM_A + q * 256 + sc * 4) = p;
    }
    __syncthreads();

    int q0 = ty * 8;

    for (int t = 0; t < 64; t++) {
        if (t + 1 < 64) {
            uint32_t bb = sb + (((t + 1) & 1) ? SM_B1 : SM_B0);
            const char* gsrc = (const char*)g_w8T + (size_t)(t + 1) * 512;
#pragma unroll
            for (int i = 0; i < 8; i++) {
                int e = tid + i * 256;
                int row = e >> 5, c16 = e & 31;
                CPASYNC(bb + row * 512 + c16 * 16, gsrc + (size_t)row * 32768 + c16 * 16);
            }
            CPCOMMIT();
            CPWAIT(1);
        } else {
            CPWAIT(0);
        }
        __syncthreads();

        const char* Bs = smem + ((t & 1) ? SM_B1 : SM_B0);

        int acc[8][8];
#pragma unroll
        for (int i = 0; i < 8; i++)
#pragma unroll
            for (int j = 0; j < 8; j++) acc[i][j] = 0;

#pragma unroll 4
        for (int g = 0; g < 16; g++) {
            uint4 qv[8];
#pragma unroll
            for (int i = 0; i < 8; i++)
                qv[i] = *(const uint4*)(smem + SM_A + (q0 + i) * 256 + (((g * 4) ^ (i << 2)) * 4));
#pragma unroll
            for (int k = 0; k < 4; k++) {
                uint4 ca = *(const uint4*)(Bs + (g * 4 + k) * 512 + tx * 32);
                uint4 cb = *(const uint4*)(Bs + (g * 4 + k) * 512 + tx * 32 + 16);
#pragma unroll
                for (int i = 0; i < 8; i++) {
                    int qk = (int)((k == 0) ? qv[i].x : (k == 1) ? qv[i].y
                                   : (k == 2) ? qv[i].z : qv[i].w);
                    acc[i][0] = __dp4a(qk, (int)ca.x, acc[i][0]);
                    acc[i][1] = __dp4a(qk, (int)ca.y, acc[i][1]);
                    acc[i][2] = __dp4a(qk, (int)ca.z, acc[i][2]);
                    acc[i][3] = __dp4a(qk, (int)ca.w, acc[i][3]);
                    acc[i][4] = __dp4a(qk, (int)cb.x, acc[i][4]);
                    acc[i][5] = __dp4a(qk, (int)cb.y, acc[i][5]);
                    acc[i][6] = __dp4a(qk, (int)cb.z, acc[i][6]);
                    acc[i][7] = __dp4a(qk, (int)cb.w, acc[i][7]);
                }
            }
        }

        // epilogue: thread's 8 codes form bin (t*16+tx); per-query bin min
        {
            float4 cnA = *(const float4*)&cn_s[t * 128 + tx * 8];
            float4 cnB = *(const float4*)&cn_s[t * 128 + tx * 8 + 4];
            int bin = t * 16 + tx;
            float bm[8];
#pragma unroll
            for (int i = 0; i < 8; i++) {
                float m0 = fminf(cnA.x - (float)acc[i][0] * C2S,
                                 cnA.y - (float)acc[i][1] * C2S);
                float m1 = fminf(cnA.z - (float)acc[i][2] * C2S,
                                 cnA.w - (float)acc[i][3] * C2S);
                float m2 = fminf(cnB.x - (float)acc[i][4] * C2S,
                                 cnB.y - (float)acc[i][5] * C2S);
                float m3 = fminf(cnB.z - (float)acc[i][6] * C2S,
                                 cnB.w - (float)acc[i][7] * C2S);
                bm[i] = fminf(fminf(m0, m1), fminf(m2, m3));
            }
            float* dst = &g_bm8[(size_t)bin * NQ + qbase + q0];
            *(float4*)dst = make_float4(bm[0], bm[1], bm[2], bm[3]);
            *(float4*)(dst + 4) = make_float4(bm[4], bm[5], bm[6], bm[7]);
        }
        __syncthreads();
    }
}

// ---------------- exact rescore ----------------
__global__ void k_rescore(const float* __restrict__ w) {
    int q = blockIdx.x * 128 + threadIdx.x;
    float m = __int_as_float(0x7f800000);
#pragma unroll 8
    for (int i = 0; i < 1024; i++) m = fminf(m, g_bm8[(size_t)i * NQ + q]);
    float thr = m + MARGIN;

    float best = __int_as_float(0x7f800000);
    int bi = 0;
    const float4* zq4 = (const float4*)(g_zT + (size_t)q * DD);
    for (int i = 0; i < 1024; i++) {
        if (g_bm8[(size_t)i * NQ + q] <= thr) {
            float acc[8];
#pragma unroll
            for (int k = 0; k < 8; k++) acc[k] = 0.f;
            const float4* wr = (const float4*)(w + (size_t)i * 8 * DD);
            for (int c4 = 0; c4 < 64; c4++) {
                float4 zv = __ldg(&zq4[c4]);
#pragma unroll
                for (int k = 0; k < 8; k++) {
                    float4 wv = __ldg(&wr[k * 64 + c4]);
                    acc[k] = fmaf(zv.x, wv.x, acc[k]);
                    acc[k] = fmaf(zv.y, wv.y, acc[k]);
                    acc[k] = fmaf(zv.z, wv.z, acc[k]);
                    acc[k] = fmaf(zv.w, wv.w, acc[k]);
                }
            }
#pragma unroll
            for (int k = 0; k < 8; k++) {
                int c = i * 8 + k;
                float sc = g_cnorm[c] - 2.f * acc[k];
                if (sc < best) { best = sc; bi = c; }
            }
        }
    }
    g_idx[q] = bi;
    atomicAdd(&g_counts[bi], 1);
}

// ---------------- gather + loss partials ----------------
__global__ void k_gather(const float* __restrict__ z, const float* __restrict__ w,
                         float* __restrict__ out) {
    int o = blockIdx.x * 256 + threadIdx.x;
    int s = o & 4095;
    int c = (o >> 12) & 255;
    int b = o >> 20;
    int n = b * 4096 + s;
    int id = g_idx[n];
    float zv = z[o];
    float wv = __ldg(w + id * DD + c);
    float d = wv - zv;
    out[o] = zv + d;

    float v = d * d;
#pragma unroll
    for (int off = 16; off; off >>= 1) v += __shfl_xor_sync(0xffffffffu, v, off);
    __shared__ float red[8];
    if ((threadIdx.x & 31) == 0) red[threadIdx.x >> 5] = v;
    __syncthreads();
    if (threadIdx.x == 0) {
        float tsum = 0.f;
#pragma unroll
        for (int i = 0; i < 8; i++) tsum += red[i];
        g_lpart[blockIdx.x] = tsum;
    }
}

__global__ void k_idxout(float* __restrict__ out) {
    int t = blockIdx.x * blockDim.x + threadIdx.x;
    if (t < NQ) out[IDX_OFF + t] = (float)g_idx[t];
}

__global__ void k_final(float* __restrict__ out) {
    __shared__ double ds[32];
    __shared__ float es[32];
    __shared__ int us[32];
    int t = threadIdx.x, lane = t & 31, warp = t >> 5;

    double lsum = 0.0;
    for (int i = t; i < 16384; i += 1024) lsum += (double)g_lpart[i];

    float ent = 0.f; int uniq = 0;
    for (int c = t; c < NC; c += 1024) {
        int cnt = g_counts[c];
        float p = (float)cnt * (1.0f / 16384.0f);
        ent += p * logf(p + 1e-10f);
        uniq += (cnt > 0);
    }
#pragma unroll
    for (int off = 16; off; off >>= 1) {
        lsum += __shfl_xor_sync(0xffffffffu, lsum, off);
        ent += __shfl_xor_sync(0xffffffffu, ent, off);
        uniq += __shfl_xor_sync(0xffffffffu, uniq, off);
    }
    if (lane == 0) { ds[warp] = lsum; es[warp] = ent; us[warp] = uniq; }
    __syncthreads();
    if (t == 0) {
        double L = 0.0; float E = 0.f; int U = 0;
        for (int i = 0; i < 32; i++) { L += ds[i]; E += es[i]; U += us[i]; }
        out[LOSS_OFF] = 0.25f * (float)(L * (1.0 / 4194304.0));
        out[PERP_OFF] = expf(-E);
        out[UNIQ_OFF] = (float)U;
    }
}

// ---------------- launch ----------------
extern "C" void kernel_launch(void* const* d_in, const int* in_sizes, int n_in,
                              void* d_out, int out_size) {
    const float* z = (const float*)d_in[0];
    const float* w = (const float*)d_in[1];
    float* out = (float*)d_out;

    cudaFuncSetAttribute(k_tc, cudaFuncAttributeMaxDynamicSharedMemorySize, SMEM_SZ);

    k_zero<<<8, 1024>>>();
    k_cnorm<<<NC / 8, 256>>>(w);
    k_w8t<<<2048, 256>>>(w);
    k_zt<<<dim3(128, 8, 4), dim3(32, 8)>>>(z);
    k_tc<<<NQ / 128, 256, SMEM_SZ>>>(z);
    k_rescore<<<NQ / 128, 128>>>(w);
    k_gather<<<ZELEMS / 256, 256>>>(z, w, out);
    k_idxout<<<16, 1024>>>(out);
    k_final<<<1, 1024>>>(out);
}